// round 14
// baseline (speedup 1.0000x reference)
#include <cuda_runtime.h>
#include <cuda_bf16.h>
#include <math.h>
#include <stdint.h>

#define NB 8
#define NF 4096
#define NQ 64
#define ND 1024
#define NH 16
#define DHD 64
#define NFL 4160            // NF + NQ
#define INNER 1024
#define MKV (NB*NFL)        // 33280
#define MQ  (NB*NQ)         // 512

// ---------------- scratch (device globals; no allocation allowed) ----------
__device__ signed char g_xq1[34078720];     // LN([feat;lat]) digit1 int8
__device__ signed char g_xq2[34078720];     // digit2
__device__ float g_xs[33280];               // per-row scale (B*FL)
__device__ __nv_bfloat16 g_lath[524288];    // LN(latents) hi, contiguous (B,Q,D)
__device__ __nv_bfloat16 g_latl[524288];
__device__ __nv_bfloat16 g_wqh[1048576], g_wql[1048576];   // Wq^T hi/lo [N,K]
__device__ __nv_bfloat16 g_woh[1048576], g_wol[1048576];   // Wo^T hi/lo
__device__ signed char g_wkq1[1048576], g_wkq2[1048576];   // Wk^T int8 digits [N,K]
__device__ signed char g_wvq1[1048576], g_wvq2[1048576];
__device__ float g_wks[1024], g_wvs[1024];                 // per-col weight scales
__device__ __nv_bfloat16 g_qh[524288], g_ql[524288];       // q proj hi/lo (scaled 1/8)
__device__ __nv_bfloat16 g_kh[34078720], g_kl[34078720];   // k proj hi/lo
__device__ __nv_bfloat16 g_vh[34078720], g_vl[34078720];   // v proj hi/lo
__device__ float g_opart[4194304];          // 128 bh * 8 splits * 64 * 64
__device__ float g_mpart[65536];
__device__ float g_lpart[65536];
__device__ __nv_bfloat16 g_ah[524288];
__device__ __nv_bfloat16 g_al[524288];

// ==================== helpers ==============================================
__device__ __forceinline__ uint32_t smem_u32(const void* p) {
    uint32_t a;
    asm("{ .reg .u64 t; cvta.to.shared.u64 t, %1; cvt.u32.u64 %0, t; }" : "=r"(a) : "l"(p));
    return a;
}
__device__ __forceinline__ void ldm_x4(uint32_t* r, uint32_t addr) {
    asm volatile("ldmatrix.sync.aligned.m8n8.x4.shared.b16 {%0,%1,%2,%3}, [%4];"
                 : "=r"(r[0]), "=r"(r[1]), "=r"(r[2]), "=r"(r[3]) : "r"(addr));
}
__device__ __forceinline__ void ldm_x2(uint32_t* r, uint32_t addr) {
    asm volatile("ldmatrix.sync.aligned.m8n8.x2.shared.b16 {%0,%1}, [%2];"
                 : "=r"(r[0]), "=r"(r[1]) : "r"(addr));
}
__device__ __forceinline__ void ldm_x2_t(uint32_t* r, uint32_t addr) {
    asm volatile("ldmatrix.sync.aligned.m8n8.x2.trans.shared.b16 {%0,%1}, [%2];"
                 : "=r"(r[0]), "=r"(r[1]) : "r"(addr));
}
__device__ __forceinline__ void mma_bf16(float* c, const uint32_t* a, const uint32_t* b) {
    asm volatile("mma.sync.aligned.m16n8k16.row.col.f32.bf16.bf16.f32 "
                 "{%0,%1,%2,%3}, {%4,%5,%6,%7}, {%8,%9}, {%0,%1,%2,%3};"
                 : "+f"(c[0]), "+f"(c[1]), "+f"(c[2]), "+f"(c[3])
                 : "r"(a[0]), "r"(a[1]), "r"(a[2]), "r"(a[3]), "r"(b[0]), "r"(b[1]));
}
__device__ __forceinline__ void mma_s8(int* c, const uint32_t* a, const uint32_t* b) {
    asm volatile("mma.sync.aligned.m16n8k32.row.col.s32.s8.s8.s32 "
                 "{%0,%1,%2,%3}, {%4,%5,%6,%7}, {%8,%9}, {%0,%1,%2,%3};"
                 : "+r"(c[0]), "+r"(c[1]), "+r"(c[2]), "+r"(c[3])
                 : "r"(a[0]), "r"(a[1]), "r"(a[2]), "r"(a[3]), "r"(b[0]), "r"(b[1]));
}
__device__ __forceinline__ uint32_t packbf(float lo, float hi) {
    uint32_t r;
    asm("cvt.rn.bf16x2.f32 %0, %1, %2;" : "=r"(r) : "f"(hi), "f"(lo));
    return r;
}

// ==================== LayerNorm -> int8 digits + latent bf16 pair ==========
__global__ __launch_bounds__(256) void ln_kernel(
    const float* __restrict__ feat, const float* __restrict__ lat,
    const float* __restrict__ lnm_w, const float* __restrict__ lnm_b,
    const float* __restrict__ lnl_w, const float* __restrict__ lnl_b)
{
    int r = blockIdx.x;
    int b = r / NFL, f = r - b * NFL;
    const float* src; const float* w; const float* bias;
    bool is_lat = (f >= NF);
    int ql = 0;
    if (!is_lat) { src = feat + (size_t)(b * NF + f) * ND; w = lnm_w; bias = lnm_b; }
    else { ql = f - NF; src = lat + (size_t)(b * NQ + ql) * ND; w = lnl_w; bias = lnl_b; }

    int t = threadIdx.x;
    float4 v = ((const float4*)src)[t];
    float s  = v.x + v.y + v.z + v.w;
    float ss = v.x*v.x + v.y*v.y + v.z*v.z + v.w*v.w;

    __shared__ float red[2][8];
    __shared__ float stat[2];
    __shared__ float smax[8];
    __shared__ float sAsh;
    #pragma unroll
    for (int o = 16; o > 0; o >>= 1) {
        s  += __shfl_down_sync(0xffffffffu, s,  o);
        ss += __shfl_down_sync(0xffffffffu, ss, o);
    }
    int wid = t >> 5, lid = t & 31;
    if (lid == 0) { red[0][wid] = s; red[1][wid] = ss; }
    __syncthreads();
    if (t == 0) {
        float a = 0.f, c = 0.f;
        #pragma unroll
        for (int i = 0; i < 8; i++) { a += red[0][i]; c += red[1][i]; }
        float mu  = a * (1.0f / ND);
        float var = c * (1.0f / ND) - mu * mu;
        stat[0] = mu; stat[1] = rsqrtf(var + 1e-5f);
    }
    __syncthreads();
    float mu = stat[0], inv = stat[1];
    float4 w4 = ((const float4*)w)[t];
    float4 b4 = ((const float4*)bias)[t];
    float o0 = (v.x - mu) * inv * w4.x + b4.x;
    float o1 = (v.y - mu) * inv * w4.y + b4.y;
    float o2 = (v.z - mu) * inv * w4.z + b4.z;
    float o3 = (v.w - mu) * inv * w4.w + b4.w;

    float am = fmaxf(fmaxf(fabsf(o0), fabsf(o1)), fmaxf(fabsf(o2), fabsf(o3)));
    #pragma unroll
    for (int o = 16; o > 0; o >>= 1)
        am = fmaxf(am, __shfl_down_sync(0xffffffffu, am, o));
    if (lid == 0) smax[wid] = am;
    __syncthreads();
    if (t == 0) {
        float m = 0.f;
        #pragma unroll
        for (int i = 0; i < 8; i++) m = fmaxf(m, smax[i]);
        float sA = fmaxf(m, 1e-20f) * (1.0f / 127.0f);
        sAsh = sA;
        g_xs[r] = sA;
    }
    __syncthreads();
    float sA = sAsh, isA = 1.0f / sA;

    float ov[4] = {o0, o1, o2, o3};
    signed char q1[4], q2[4];
    #pragma unroll
    for (int i = 0; i < 4; i++) {
        float a1 = rintf(ov[i] * isA);
        a1 = fminf(fmaxf(a1, -127.f), 127.f);
        float rres = ov[i] - sA * a1;
        float a2 = rintf(rres * 128.0f * isA);
        q1[i] = (signed char)(int)a1;
        q2[i] = (signed char)(int)a2;
    }
    size_t idx = (size_t)r * ND + t * 4;
    *(char4*)&g_xq1[idx] = make_char4(q1[0], q1[1], q1[2], q1[3]);
    *(char4*)&g_xq2[idx] = make_char4(q2[0], q2[1], q2[2], q2[3]);

    if (is_lat) {
        __nv_bfloat16 h0 = __float2bfloat16(o0), h1 = __float2bfloat16(o1);
        __nv_bfloat16 h2 = __float2bfloat16(o2), h3 = __float2bfloat16(o3);
        __nv_bfloat16 l0 = __float2bfloat16(o0 - __bfloat162float(h0));
        __nv_bfloat16 l1 = __float2bfloat16(o1 - __bfloat162float(h1));
        __nv_bfloat16 l2 = __float2bfloat16(o2 - __bfloat162float(h2));
        __nv_bfloat16 l3 = __float2bfloat16(o3 - __bfloat162float(h3));
        size_t li = (size_t)(b * NQ + ql) * ND + t * 4;
        *(__nv_bfloat162*)&g_lath[li]     = __nv_bfloat162{h0, h1};
        *(__nv_bfloat162*)&g_lath[li + 2] = __nv_bfloat162{h2, h3};
        *(__nv_bfloat162*)&g_latl[li]     = __nv_bfloat162{l0, l1};
        *(__nv_bfloat162*)&g_latl[li + 2] = __nv_bfloat162{l2, l3};
    }
}

// ============ bf16 weight transpose + split (Wq, Wo) =======================
__global__ __launch_bounds__(256) void wsplit_kernel(
    const float* __restrict__ W, __nv_bfloat16* __restrict__ Th,
    __nv_bfloat16* __restrict__ Tl)
{
    __shared__ float t[32][33];
    int bx = blockIdx.x * 32;
    int by = blockIdx.y * 32;
    int tx = threadIdx.x & 31, ty = threadIdx.x >> 5;
    #pragma unroll
    for (int i = 0; i < 32; i += 8)
        t[ty + i][tx] = W[(size_t)(by + ty + i) * 1024 + bx + tx];
    __syncthreads();
    #pragma unroll
    for (int i = 0; i < 32; i += 8) {
        float v = t[tx][ty + i];
        __nv_bfloat16 h = __float2bfloat16(v);
        __nv_bfloat16 l = __float2bfloat16(v - __bfloat162float(h));
        size_t o = (size_t)(bx + ty + i) * 1024 + by + tx;
        Th[o] = h; Tl[o] = l;
    }
}

// ============ per-column weight max scale ==================================
__global__ __launch_bounds__(256) void wcolmax_kernel(
    const float* __restrict__ W, float* __restrict__ sB)
{
    int n = blockIdx.x;
    int t = threadIdx.x;
    float m = 0.f;
    for (int k = t; k < 1024; k += 256)
        m = fmaxf(m, fabsf(W[(size_t)k * 1024 + n]));
    __shared__ float red[8];
    #pragma unroll
    for (int o = 16; o > 0; o >>= 1)
        m = fmaxf(m, __shfl_down_sync(0xffffffffu, m, o));
    if ((t & 31) == 0) red[t >> 5] = m;
    __syncthreads();
    if (t == 0) {
        float mm = 0.f;
        #pragma unroll
        for (int i = 0; i < 8; i++) mm = fmaxf(mm, red[i]);
        sB[n] = fmaxf(mm, 1e-20f) * (1.0f / 127.0f);
    }
}

// ============ int8 weight transpose + 2-digit quantize =====================
__global__ __launch_bounds__(256) void wsplit_i8_kernel(
    const float* __restrict__ W, const float* __restrict__ sB,
    signed char* __restrict__ T1, signed char* __restrict__ T2)
{
    __shared__ float t[32][33];
    int bx = blockIdx.x * 32;           // n tile
    int by = blockIdx.y * 32;           // k tile
    int tx = threadIdx.x & 31, ty = threadIdx.x >> 5;
    #pragma unroll
    for (int i = 0; i < 32; i += 8)
        t[ty + i][tx] = W[(size_t)(by + ty + i) * 1024 + bx + tx];
    __syncthreads();
    #pragma unroll
    for (int i = 0; i < 32; i += 8) {
        int n = bx + ty + i;
        float s = sB[n], is = 1.0f / s;
        float v = t[tx][ty + i];        // (k = by+tx, n)
        float a1 = rintf(v * is);
        a1 = fminf(fmaxf(a1, -127.f), 127.f);
        float rres = v - s * a1;
        float a2 = rintf(rres * 128.0f * is);
        size_t o = (size_t)n * 1024 + by + tx;
        T1[o] = (signed char)(int)a1;
        T2[o] = (signed char)(int)a2;
    }
}

// ==================== bf16 split GEMM on mma.sync (Q / O projections) ======
#define LDT 40
#define VHALVES (128 * LDT)
#define STGH (4 * VHALVES)
#define GEMM_SMEM_BYTES (2 * STGH * 2)   // 81920

__device__ __forceinline__ void cp_var(uint32_t sb, uint32_t dsth,
                                       const __nv_bfloat16* __restrict__ src,
                                       int row0, int kt, int tid)
{
    #pragma unroll
    for (int j = 0; j < 2; j++) {
        int ci = tid + j * 256;
        int row = ci >> 2, c = ci & 3;
        uint32_t so = sb + (dsth + row * LDT + c * 8) * 2;
        const __nv_bfloat16* gp = src + (size_t)(row0 + row) * 1024 + kt * 32 + c * 8;
        asm volatile("cp.async.cg.shared.global [%0], [%1], 16;" :: "r"(so), "l"(gp));
    }
}

__global__ __launch_bounds__(256)
void gemm_mma_kernel(const __nv_bfloat16* __restrict__ Ah, const __nv_bfloat16* __restrict__ Al,
                     const __nv_bfloat16* __restrict__ Bh, const __nv_bfloat16* __restrict__ Bl,
                     float* __restrict__ Cf, __nv_bfloat16* __restrict__ Ch,
                     __nv_bfloat16* __restrict__ Cl, float alpha)
{
    extern __shared__ __nv_bfloat16 smn[];
    uint32_t sb = smem_u32(smn);
    int tid = threadIdx.x;
    int lid = tid & 31;
    int wid = tid >> 5;
    int warp_m = wid >> 2;
    int warp_n = wid & 3;
    int bm = blockIdx.y * 128;
    int bn = blockIdx.x * 128;

    float acc[4][4][4];
    #pragma unroll
    for (int i = 0; i < 4; i++)
        #pragma unroll
        for (int j = 0; j < 4; j++)
            #pragma unroll
            for (int k = 0; k < 4; k++) acc[i][j][k] = 0.f;

    const int NT = 32;
    {
        uint32_t st = 0;
        cp_var(sb, st,               Ah, bm, 0, tid);
        cp_var(sb, st + VHALVES,     Al, bm, 0, tid);
        cp_var(sb, st + 2 * VHALVES, Bh, bn, 0, tid);
        cp_var(sb, st + 3 * VHALVES, Bl, bn, 0, tid);
        asm volatile("cp.async.commit_group;" ::: "memory");
    }
    int a_row = lid & 15, a_koff = (lid >> 4) * 8;
    int b_row = lid & 7,  b_koff = ((lid >> 3) & 1) * 8;

    for (int kt = 0; kt < NT; ++kt) {
        if (kt + 1 < NT) {
            uint32_t st = ((kt + 1) & 1) * STGH;
            cp_var(sb, st,               Ah, bm, kt + 1, tid);
            cp_var(sb, st + VHALVES,     Al, bm, kt + 1, tid);
            cp_var(sb, st + 2 * VHALVES, Bh, bn, kt + 1, tid);
            cp_var(sb, st + 3 * VHALVES, Bl, bn, kt + 1, tid);
            asm volatile("cp.async.commit_group;" ::: "memory");
            asm volatile("cp.async.wait_group 1;" ::: "memory");
        } else {
            asm volatile("cp.async.wait_group 0;" ::: "memory");
        }
        __syncthreads();

        uint32_t st = (kt & 1) * STGH;
        uint32_t Ah_b = sb + (st) * 2;
        uint32_t Al_b = sb + (st + VHALVES) * 2;
        uint32_t Bh_b = sb + (st + 2 * VHALVES) * 2;
        uint32_t Bl_b = sb + (st + 3 * VHALVES) * 2;

        #pragma unroll
        for (int ks = 0; ks < 2; ++ks) {
            uint32_t ah[4][4], al[4][4], bf[4][2];
            #pragma unroll
            for (int mt = 0; mt < 4; mt++) {
                uint32_t off = ((warp_m * 64 + mt * 16 + a_row) * LDT + ks * 16 + a_koff) * 2;
                ldm_x4(ah[mt], Ah_b + off);
            }
            #pragma unroll
            for (int nt = 0; nt < 4; nt++) {
                uint32_t off = ((warp_n * 32 + nt * 8 + b_row) * LDT + ks * 16 + b_koff) * 2;
                ldm_x2(bf[nt], Bh_b + off);
            }
            #pragma unroll
            for (int mt = 0; mt < 4; mt++)
                #pragma unroll
                for (int nt = 0; nt < 4; nt++) mma_bf16(acc[mt][nt], ah[mt], bf[nt]);
            #pragma unroll
            for (int mt = 0; mt < 4; mt++) {
                uint32_t off = ((warp_m * 64 + mt * 16 + a_row) * LDT + ks * 16 + a_koff) * 2;
                ldm_x4(al[mt], Al_b + off);
            }
            #pragma unroll
            for (int mt = 0; mt < 4; mt++)
                #pragma unroll
                for (int nt = 0; nt < 4; nt++) mma_bf16(acc[mt][nt], al[mt], bf[nt]);
            #pragma unroll
            for (int nt = 0; nt < 4; nt++) {
                uint32_t off = ((warp_n * 32 + nt * 8 + b_row) * LDT + ks * 16 + b_koff) * 2;
                ldm_x2(bf[nt], Bl_b + off);
            }
            #pragma unroll
            for (int mt = 0; mt < 4; mt++)
                #pragma unroll
                for (int nt = 0; nt < 4; nt++) mma_bf16(acc[mt][nt], ah[mt], bf[nt]);
        }
        __syncthreads();
    }

    int r0 = bm + warp_m * 64 + (lid >> 2);
    int c0 = bn + warp_n * 32 + (lid & 3) * 2;
    if (Cf) {
        #pragma unroll
        for (int mt = 0; mt < 4; mt++) {
            #pragma unroll
            for (int nt = 0; nt < 4; nt++) {
                float* p0 = Cf + (size_t)(r0 + mt * 16) * 1024 + c0 + nt * 8;
                float* p1 = Cf + (size_t)(r0 + mt * 16 + 8) * 1024 + c0 + nt * 8;
                *(float2*)p0 = make_float2(alpha * acc[mt][nt][0], alpha * acc[mt][nt][1]);
                *(float2*)p1 = make_float2(alpha * acc[mt][nt][2], alpha * acc[mt][nt][3]);
            }
        }
    } else {
        #pragma unroll
        for (int mt = 0; mt < 4; mt++) {
            #pragma unroll
            for (int nt = 0; nt < 4; nt++) {
                #pragma unroll
                for (int half = 0; half < 2; half++) {
                    float v0 = alpha * acc[mt][nt][half * 2];
                    float v1 = alpha * acc[mt][nt][half * 2 + 1];
                    __nv_bfloat16 h0 = __float2bfloat16(v0), h1 = __float2bfloat16(v1);
                    __nv_bfloat16 l0 = __float2bfloat16(v0 - __bfloat162float(h0));
                    __nv_bfloat16 l1 = __float2bfloat16(v1 - __bfloat162float(h1));
                    size_t o = (size_t)(r0 + mt * 16 + half * 8) * 1024 + c0 + nt * 8;
                    *(__nv_bfloat162*)&Ch[o] = __nv_bfloat162{h0, h1};
                    *(__nv_bfloat162*)&Cl[o] = __nv_bfloat162{l0, l1};
                }
            }
        }
    }
}

// ============ int8 2-digit GEMM, BK=64, K/V via blockIdx.z =================
#define QLDB 80                        // smem row stride bytes (64 data + 16 pad)
#define QTILEB (128 * QLDB)            // 10240 B per tile
#define QSTGB (4 * QTILEB)             // 40960 B per stage (A1,A2,B1,B2)
#define QSTAGES 3
#define GEMM_I8_SMEM (QSTAGES * QSTGB) // 122880

__device__ __forceinline__ void cp_stage_i8(uint32_t sb, int slot,
    const signed char* __restrict__ A1, const signed char* __restrict__ A2,
    const signed char* __restrict__ B1, const signed char* __restrict__ B2,
    int bm, int bn, int kt, int tid)
{
    uint32_t base = sb + slot * QSTGB;
    #pragma unroll
    for (int t4 = 0; t4 < 4; t4++) {
        const signed char* src = (t4 == 0) ? A1 : (t4 == 1) ? A2 : (t4 == 2) ? B1 : B2;
        int r0 = (t4 < 2) ? bm : bn;
        #pragma unroll
        for (int u = 0; u < 2; u++) {
            int idx = tid + u * 256;          // 0..511 16B chunks (128 rows x 4)
            int row = idx >> 2, c = idx & 3;
            uint32_t dst = base + t4 * QTILEB + row * QLDB + c * 16;
            const signed char* gp = src + (size_t)(r0 + row) * 1024 + kt * 64 + c * 16;
            asm volatile("cp.async.cg.shared.global [%0], [%1], 16;" :: "r"(dst), "l"(gp));
        }
    }
}

__global__ __launch_bounds__(256, 1)
void gemm_i8_kernel(const signed char* __restrict__ A1, const signed char* __restrict__ A2,
                    const float* __restrict__ sA,
                    const signed char* __restrict__ Bk1, const signed char* __restrict__ Bk2,
                    const float* __restrict__ sBk,
                    const signed char* __restrict__ Bv1, const signed char* __restrict__ Bv2,
                    const float* __restrict__ sBv,
                    __nv_bfloat16* __restrict__ Kh, __nv_bfloat16* __restrict__ Kl,
                    __nv_bfloat16* __restrict__ Vh, __nv_bfloat16* __restrict__ Vl)
{
    extern __shared__ signed char smq[];
    uint32_t sb = smem_u32(smq);
    int tid = threadIdx.x;
    int lid = tid & 31;
    int wid = tid >> 5;
    int warp_m = wid >> 2;            // 0..1 (64 rows)
    int warp_n = wid & 3;             // 0..3 (32 cols)
    int bm = blockIdx.y * 128;
    int bn = blockIdx.x * 128;
    int zv = blockIdx.z;              // 0 = K, 1 = V

    const signed char* B1 = zv ? Bv1 : Bk1;
    const signed char* B2 = zv ? Bv2 : Bk2;
    const float* sB       = zv ? sBv : sBk;
    __nv_bfloat16* Ch     = zv ? Vh : Kh;
    __nv_bfloat16* Cl     = zv ? Vl : Kl;

    int S1[4][4][4], S2[4][4][4];
    #pragma unroll
    for (int i = 0; i < 4; i++)
        #pragma unroll
        for (int j = 0; j < 4; j++)
            #pragma unroll
            for (int k = 0; k < 4; k++) { S1[i][j][k] = 0; S2[i][j][k] = 0; }

    const int NT = 16;                // 1024 / BK64
    cp_stage_i8(sb, 0, A1, A2, B1, B2, bm, bn, 0, tid);
    asm volatile("cp.async.commit_group;" ::: "memory");
    cp_stage_i8(sb, 1, A1, A2, B1, B2, bm, bn, 1, tid);
    asm volatile("cp.async.commit_group;" ::: "memory");

    int aRow  = (lid < 16) ? lid : (lid - 16);     // 0..15
    int aByte = (lid < 16) ? 0 : 16;
    int bRow  = lid & 7;
    int bByte = ((lid >> 3) & 1) * 16;

    for (int kt = 0; kt < NT; ++kt) {
        if (kt + 1 < NT) asm volatile("cp.async.wait_group 1;" ::: "memory");
        else             asm volatile("cp.async.wait_group 0;" ::: "memory");
        __syncthreads();
        if (kt + 2 < NT) {
            cp_stage_i8(sb, (kt + 2) % QSTAGES, A1, A2, B1, B2, bm, bn, kt + 2, tid);
            asm volatile("cp.async.commit_group;" ::: "memory");
        }

        uint32_t tb  = sb + (kt % QSTAGES) * QSTGB;
        uint32_t A1b = tb;
        uint32_t A2b = tb + QTILEB;
        uint32_t B1b = tb + 2 * QTILEB;
        uint32_t B2b = tb + 3 * QTILEB;

        #pragma unroll
        for (int ks = 0; ks < 2; ++ks) {          // two k32 halves of BK=64
            uint32_t a1f[4][4], a2f[4][4], b1f[4][2], b2f[4][2];
            #pragma unroll
            for (int mt = 0; mt < 4; mt++) {
                uint32_t off = (uint32_t)(warp_m * 64 + mt * 16 + aRow) * QLDB
                               + ks * 32 + aByte;
                ldm_x4(a1f[mt], A1b + off);
                ldm_x4(a2f[mt], A2b + off);
            }
            #pragma unroll
            for (int nt = 0; nt < 4; nt++) {
                uint32_t off = (uint32_t)(warp_n * 32 + nt * 8 + bRow) * QLDB
                               + ks * 32 + bByte;
                ldm_x2(b1f[nt], B1b + off);
                ldm_x2(b2f[nt], B2b + off);
            }
            #pragma unroll
            for (int mt = 0; mt < 4; mt++)
                #pragma unroll
                for (int nt = 0; nt < 4; nt++) mma_s8(S1[mt][nt], a1f[mt], b1f[nt]);
            #pragma unroll
            for (int mt = 0; mt < 4; mt++)
                #pragma unroll
                for (int nt = 0; nt < 4; nt++) mma_s8(S2[mt][nt], a1f[mt], b2f[nt]);
            #pragma unroll
            for (int mt = 0; mt < 4; mt++)
                #pragma unroll
                for (int nt = 0; nt < 4; nt++) mma_s8(S2[mt][nt], a2f[mt], b1f[nt]);
        }
        __syncthreads();
    }

    // epilogue: dequant + bf16 hi/lo
    int r0 = bm + warp_m * 64 + (lid >> 2);
    int c0 = bn + warp_n * 32 + (lid & 3) * 2;
    #pragma unroll
    for (int mt = 0; mt < 4; mt++) {
        float sa0 = sA[r0 + mt * 16];
        float sa1 = sA[r0 + mt * 16 + 8];
        #pragma unroll
        for (int nt = 0; nt < 4; nt++) {
            float sb0 = sB[c0 + nt * 8];
            float sb1 = sB[c0 + nt * 8 + 1];
            #pragma unroll
            for (int half = 0; half < 2; half++) {
                float sar = half ? sa1 : sa0;
                float v0 = sar * sb0 * ((float)S1[mt][nt][half * 2]     + (float)S2[mt][nt][half * 2]     * 0.0078125f);
                float v1 = sar * sb1 * ((float)S1[mt][nt][half * 2 + 1] + (float)S2[mt][nt][half * 2 + 1] * 0.0078125f);
                __nv_bfloat16 h0 = __float2bfloat16(v0), h1 = __float2bfloat16(v1);
                __nv_bfloat16 l0 = __float2bfloat16(v0 - __bfloat162float(h0));
                __nv_bfloat16 l1 = __float2bfloat16(v1 - __bfloat162float(h1));
                size_t o = (size_t)(r0 + mt * 16 + half * 8) * 1024 + c0 + nt * 8;
                *(__nv_bfloat162*)&Ch[o] = __nv_bfloat162{h0, h1};
                *(__nv_bfloat162*)&Cl[o] = __nv_bfloat162{l0, l1};
            }
        }
    }
}

// ==================== tensor-core flash attention, split-KV=8 ==============
#define NSPLIT 8
#define CPS 9
#define ASTR 72
#define QTILE (64 * ASTR)
#define ATTN_SMEM ((2 * QTILE + 2 * 4 * QTILE) * 2)   // 92160

__device__ __forceinline__ void stage_kv(uint32_t sb, uint32_t stbase,
    const __nv_bfloat16* kh, const __nv_bfloat16* kl,
    const __nv_bfloat16* vh, const __nv_bfloat16* vl, size_t off, int tid)
{
    const __nv_bfloat16* srcs[4] = {kh, kl, vh, vl};
    #pragma unroll
    for (int j = 0; j < 16; j++) {
        int ci = tid + j * 128;
        int tile = ci >> 9, row = (ci >> 3) & 63, c = ci & 7;
        uint32_t dst = sb + (stbase + tile * QTILE + row * ASTR) * 2 + c * 16;
        const __nv_bfloat16* src = srcs[tile] + off + (size_t)row * INNER + c * 8;
        asm volatile("cp.async.cg.shared.global [%0], [%1], 16;" :: "r"(dst), "l"(src));
    }
}

__global__ __launch_bounds__(128) void attn_kernel()
{
    extern __shared__ __nv_bfloat16 asmem[];
    uint32_t sb = smem_u32(asmem);
    const uint32_t QH = 0, QL = QTILE, ST0 = 2 * QTILE;

    int tid = threadIdx.x, lid = tid & 31, wid = tid >> 5;
    int bh = blockIdx.x, b = bh >> 4, h = bh & 15;
    int sp = blockIdx.y;
    int c0 = sp * CPS, c1 = min(65, c0 + CPS);

    const __nv_bfloat16* qhg = g_qh + (size_t)(b * NQ) * INNER + h * DHD;
    const __nv_bfloat16* qlg = g_ql + (size_t)(b * NQ) * INNER + h * DHD;
    const __nv_bfloat16* khg = g_kh + (size_t)(b * NFL) * INNER + h * DHD;
    const __nv_bfloat16* klg = g_kl + (size_t)(b * NFL) * INNER + h * DHD;
    const __nv_bfloat16* vhg = g_vh + (size_t)(b * NFL) * INNER + h * DHD;
    const __nv_bfloat16* vlg = g_vl + (size_t)(b * NFL) * INNER + h * DHD;

    #pragma unroll
    for (int j = 0; j < 8; j++) {
        int ci = tid + j * 128;
        int tile = ci >> 9, row = (ci >> 3) & 63, c = ci & 7;
        uint32_t dst = sb + ((tile ? QL : QH) + row * ASTR) * 2 + c * 16;
        const __nv_bfloat16* src = (tile ? qlg : qhg) + (size_t)row * INNER + c * 8;
        asm volatile("cp.async.cg.shared.global [%0], [%1], 16;" :: "r"(dst), "l"(src));
    }
    stage_kv(sb, ST0, khg, klg, vhg, vlg, (size_t)c0 * 64 * INNER, tid);
    asm volatile("cp.async.commit_group;" ::: "memory");

    float oc[8][4];
    #pragma unroll
    for (int i = 0; i < 8; i++)
        #pragma unroll
        for (int j = 0; j < 4; j++) oc[i][j] = 0.f;
    float m0 = -1e30f, m1 = -1e30f, l0 = 0.f, l1 = 0.f;

    uint32_t qhf[4][4], qlf[4][4];
    bool qloaded = false;

    for (int c = c0; c < c1; ++c) {
        int p = (c - c0) & 1;
        if (c + 1 < c1) {
            stage_kv(sb, ST0 + (1 - p) * 4 * QTILE, khg, klg, vhg, vlg,
                     (size_t)(c + 1) * 64 * INNER, tid);
            asm volatile("cp.async.commit_group;" ::: "memory");
            asm volatile("cp.async.wait_group 1;" ::: "memory");
        } else {
            asm volatile("cp.async.wait_group 0;" ::: "memory");
        }
        __syncthreads();

        if (!qloaded) {
            #pragma unroll
            for (int t = 0; t < 4; t++) {
                uint32_t ao = ((wid * 16 + (lid & 15)) * ASTR + t * 16 + (lid >> 4) * 8) * 2;
                ldm_x4(qhf[t], sb + QH * 2 + ao);
                ldm_x4(qlf[t], sb + QL * 2 + ao);
            }
            qloaded = true;
        }
        uint32_t stb = ST0 + p * 4 * QTILE;

        float sc[8][4];
        #pragma unroll
        for (int j = 0; j < 8; j++)
            #pragma unroll
            for (int k = 0; k < 4; k++) sc[j][k] = 0.f;
        #pragma unroll
        for (int t = 0; t < 4; t++) {
            #pragma unroll
            for (int j = 0; j < 8; j++) {
                uint32_t ko = ((8 * j + (lid & 7)) * ASTR + t * 16 + ((lid >> 3) & 1) * 8) * 2;
                uint32_t bK[2], bKl[2];
                ldm_x2(bK,  sb + stb * 2 + ko);
                ldm_x2(bKl, sb + (stb + QTILE) * 2 + ko);
                mma_bf16(sc[j], qhf[t], bK);
                mma_bf16(sc[j], qlf[t], bK);
                mma_bf16(sc[j], qhf[t], bKl);
            }
        }
        float cm0 = -1e30f, cm1 = -1e30f;
        #pragma unroll
        for (int j = 0; j < 8; j++) {
            cm0 = fmaxf(cm0, fmaxf(sc[j][0], sc[j][1]));
            cm1 = fmaxf(cm1, fmaxf(sc[j][2], sc[j][3]));
        }
        cm0 = fmaxf(cm0, __shfl_xor_sync(0xffffffffu, cm0, 1));
        cm0 = fmaxf(cm0, __shfl_xor_sync(0xffffffffu, cm0, 2));
        cm1 = fmaxf(cm1, __shfl_xor_sync(0xffffffffu, cm1, 1));
        cm1 = fmaxf(cm1, __shfl_xor_sync(0xffffffffu, cm1, 2));
        float nm0 = fmaxf(m0, cm0), nm1 = fmaxf(m1, cm1);
        float sum0 = 0.f, sum1 = 0.f;
        #pragma unroll
        for (int j = 0; j < 8; j++) {
            sc[j][0] = __expf(sc[j][0] - nm0);
            sc[j][1] = __expf(sc[j][1] - nm0);
            sc[j][2] = __expf(sc[j][2] - nm1);
            sc[j][3] = __expf(sc[j][3] - nm1);
            sum0 += sc[j][0] + sc[j][1];
            sum1 += sc[j][2] + sc[j][3];
        }
        sum0 += __shfl_xor_sync(0xffffffffu, sum0, 1);
        sum0 += __shfl_xor_sync(0xffffffffu, sum0, 2);
        sum1 += __shfl_xor_sync(0xffffffffu, sum1, 1);
        sum1 += __shfl_xor_sync(0xffffffffu, sum1, 2);
        float e0 = __expf(m0 - nm0), e1 = __expf(m1 - nm1);
        l0 = l0 * e0 + sum0; l1 = l1 * e1 + sum1;
        m0 = nm0; m1 = nm1;
        #pragma unroll
        for (int nd = 0; nd < 8; nd++) {
            oc[nd][0] *= e0; oc[nd][1] *= e0;
            oc[nd][2] *= e1; oc[nd][3] *= e1;
        }
        uint32_t vstb = stb + 2 * QTILE;
        #pragma unroll
        for (int t2 = 0; t2 < 4; t2++) {
            float ph[8], pl[8];
            #pragma unroll
            for (int u = 0; u < 2; u++) {
                #pragma unroll
                for (int k = 0; k < 4; k++) {
                    float v = sc[2 * t2 + u][k];
                    __nv_bfloat16 hb = __float2bfloat16(v);
                    float hf = __bfloat162float(hb);
                    ph[u * 4 + k] = hf;
                    pl[u * 4 + k] = v - hf;
                }
            }
            uint32_t aph[4], apl[4];
            aph[0] = packbf(ph[0], ph[1]); aph[1] = packbf(ph[2], ph[3]);
            aph[2] = packbf(ph[4], ph[5]); aph[3] = packbf(ph[6], ph[7]);
            apl[0] = packbf(pl[0], pl[1]); apl[1] = packbf(pl[2], pl[3]);
            apl[2] = packbf(pl[4], pl[5]); apl[3] = packbf(pl[6], pl[7]);
            #pragma unroll
            for (int nd = 0; nd < 8; nd++) {
                uint32_t vo = ((16 * t2 + (lid & 15)) * ASTR + nd * 8) * 2;
                uint32_t bV[2], bVl[2];
                ldm_x2_t(bV,  sb + vstb * 2 + vo);
                ldm_x2_t(bVl, sb + (vstb + QTILE) * 2 + vo);
                mma_bf16(oc[nd], aph, bV);
                mma_bf16(oc[nd], apl, bV);
                mma_bf16(oc[nd], aph, bVl);
            }
        }
        __syncthreads();
    }
    float i0 = 1.0f / l0, i1 = 1.0f / l1;
    int pidx = bh * NSPLIT + sp;
    int r0 = wid * 16 + (lid >> 2), r1 = r0 + 8;
    #pragma unroll
    for (int nd = 0; nd < 8; nd++) {
        int col = 8 * nd + (lid & 3) * 2;
        *(float2*)&g_opart[((size_t)pidx * 64 + r0) * 64 + col] =
            make_float2(oc[nd][0] * i0, oc[nd][1] * i0);
        *(float2*)&g_opart[((size_t)pidx * 64 + r1) * 64 + col] =
            make_float2(oc[nd][2] * i1, oc[nd][3] * i1);
    }
    if ((lid & 3) == 0) {
        g_mpart[pidx * 64 + r0] = m0; g_lpart[pidx * 64 + r0] = l0;
        g_mpart[pidx * 64 + r1] = m1; g_lpart[pidx * 64 + r1] = l1;
    }
}

// ---------------- merge splits -> attn out hi/lo ---------------------------
__global__ __launch_bounds__(256) void attn_merge_kernel()
{
    int bh = blockIdx.x;
    int b = bh >> 4, h = bh & 15;
    int row = threadIdx.x >> 2;
    int cg  = threadIdx.x & 3;
    float m[NSPLIT], l[NSPLIT];
    #pragma unroll
    for (int s = 0; s < NSPLIT; s++) {
        m[s] = g_mpart[(bh * NSPLIT + s) * 64 + row];
        l[s] = g_lpart[(bh * NSPLIT + s) * 64 + row];
    }
    float M = m[0];
    #pragma unroll
    for (int s = 1; s < NSPLIT; s++) M = fmaxf(M, m[s]);
    float w[NSPLIT]; float L = 0.f;
    #pragma unroll
    for (int s = 0; s < NSPLIT; s++) { w[s] = __expf(m[s] - M); L += w[s] * l[s]; }
    float inv = 1.0f / L;
    #pragma unroll
    for (int j = 0; j < 16; j++) {
        int col = cg * 16 + j;
        float acc = 0.f;
        #pragma unroll
        for (int s = 0; s < NSPLIT; s++)
            acc += g_opart[((size_t)(bh * NSPLIT + s) * 64 + row) * 64 + col] * w[s] * l[s];
        acc *= inv;
        __nv_bfloat16 hh = __float2bfloat16(acc);
        size_t oidx = (size_t)(b * NQ + row) * INNER + h * DHD + col;
        g_ah[oidx] = hh;
        g_al[oidx] = __float2bfloat16(acc - __bfloat162float(hh));
    }
}

// ==================== launcher =============================================
extern "C" void kernel_launch(void* const* d_in, const int* in_sizes, int n_in,
                              void* d_out, int out_size)
{
    const float* features = (const float*)d_in[0];
    const float* latents  = (const float*)d_in[1];
    const float* lnm_w    = (const float*)d_in[2];
    const float* lnm_b    = (const float*)d_in[3];
    const float* lnl_w    = (const float*)d_in[4];
    const float* lnl_b    = (const float*)d_in[5];
    const float* Wq       = (const float*)d_in[6];
    const float* Wk       = (const float*)d_in[7];
    const float* Wv       = (const float*)d_in[8];
    const float* Wo       = (const float*)d_in[9];
    float* out = (float*)d_out;

    __nv_bfloat16 *p_lath, *p_latl, *p_wqh, *p_wql, *p_woh, *p_wol;
    __nv_bfloat16 *p_ah, *p_al, *p_qh, *p_ql, *p_kh, *p_kl, *p_vh, *p_vl;
    signed char *p_xq1, *p_xq2, *p_wkq1, *p_wkq2, *p_wvq1, *p_wvq2;
    float *p_xs, *p_wks, *p_wvs;
    cudaGetSymbolAddress((void**)&p_lath, g_lath); cudaGetSymbolAddress((void**)&p_latl, g_latl);
    cudaGetSymbolAddress((void**)&p_wqh, g_wqh); cudaGetSymbolAddress((void**)&p_wql, g_wql);
    cudaGetSymbolAddress((void**)&p_woh, g_woh); cudaGetSymbolAddress((void**)&p_wol, g_wol);
    cudaGetSymbolAddress((void**)&p_ah, g_ah);   cudaGetSymbolAddress((void**)&p_al, g_al);
    cudaGetSymbolAddress((void**)&p_qh, g_qh);   cudaGetSymbolAddress((void**)&p_ql, g_ql);
    cudaGetSymbolAddress((void**)&p_kh, g_kh);   cudaGetSymbolAddress((void**)&p_kl, g_kl);
    cudaGetSymbolAddress((void**)&p_vh, g_vh);   cudaGetSymbolAddress((void**)&p_vl, g_vl);
    cudaGetSymbolAddress((void**)&p_xq1, g_xq1); cudaGetSymbolAddress((void**)&p_xq2, g_xq2);
    cudaGetSymbolAddress((void**)&p_wkq1, g_wkq1); cudaGetSymbolAddress((void**)&p_wkq2, g_wkq2);
    cudaGetSymbolAddress((void**)&p_wvq1, g_wvq1); cudaGetSymbolAddress((void**)&p_wvq2, g_wvq2);
    cudaGetSymbolAddress((void**)&p_xs, g_xs);
    cudaGetSymbolAddress((void**)&p_wks, g_wks); cudaGetSymbolAddress((void**)&p_wvs, g_wvs);

    cudaFuncSetAttribute(gemm_mma_kernel,
                         cudaFuncAttributeMaxDynamicSharedMemorySize, GEMM_SMEM_BYTES);
    cudaFuncSetAttribute(gemm_i8_kernel,
                         cudaFuncAttributeMaxDynamicSharedMemorySize, GEMM_I8_SMEM);
    cudaFuncSetAttribute(attn_kernel,
                         cudaFuncAttributeMaxDynamicSharedMemorySize, ATTN_SMEM);

    // 1) LayerNorm -> int8 digits (+ latent bf16 pair)
    ln_kernel<<<NB * NFL, 256>>>(features, latents, lnm_w, lnm_b, lnl_w, lnl_b);

    // 2) weight prep
    dim3 gW(32, 32);
    wsplit_kernel<<<gW, 256>>>(Wq, p_wqh, p_wql);
    wsplit_kernel<<<gW, 256>>>(Wo, p_woh, p_wol);
    wcolmax_kernel<<<1024, 256>>>(Wk, p_wks);
    wcolmax_kernel<<<1024, 256>>>(Wv, p_wvs);
    wsplit_i8_kernel<<<gW, 256>>>(Wk, p_wks, p_wkq1, p_wkq2);
    wsplit_i8_kernel<<<gW, 256>>>(Wv, p_wvs, p_wvq1, p_wvq2);

    // 3) K + V projections: one launch, BK=64, z selects K/V
    dim3 gKV(8, MKV / 128, 2);
    gemm_i8_kernel<<<gKV, 256, GEMM_I8_SMEM>>>(p_xq1, p_xq2, p_xs,
                                               p_wkq1, p_wkq2, p_wks,
                                               p_wvq1, p_wvq2, p_wvs,
                                               p_kh, p_kl, p_vh, p_vl);

    // 4) Q projection (bf16 path, scale folded)
    dim3 gQ(8, MQ / 128);
    gemm_mma_kernel<<<gQ, 256, GEMM_SMEM_BYTES>>>(p_lath, p_latl, p_wqh, p_wql,
                                                  nullptr, p_qh, p_ql, 0.125f);

    // 5) attention split-KV=8 + merge
    dim3 gA(NB * NH, NSPLIT);
    attn_kernel<<<gA, 128, ATTN_SMEM>>>();
    attn_merge_kernel<<<NB * NH, 256>>>();

    // 6) output projection -> fp32 out
    gemm_mma_kernel<<<gQ, 256, GEMM_SMEM_BYTES>>>(p_ah, p_al, p_woh, p_wol,
                                                  out, nullptr, nullptr, 1.0f);
}

// round 16
// speedup vs baseline: 1.0088x; 1.0088x over previous
#include <cuda_runtime.h>
#include <cuda_bf16.h>
#include <math.h>
#include <stdint.h>

#define NB 8
#define NF 4096
#define NQ 64
#define ND 1024
#define NH 16
#define DHD 64
#define NFL 4160            // NF + NQ
#define INNER 1024
#define MKV (NB*NFL)        // 33280
#define MQ  (NB*NQ)         // 512

// ---------------- scratch (device globals; no allocation allowed) ----------
__device__ signed char g_xq1[34078720];     // LN([feat;lat]) digit1 int8
__device__ signed char g_xq2[34078720];     // digit2
__device__ float g_xs[33280];               // per-row scale (B*FL)
__device__ __nv_bfloat16 g_lath[524288];    // LN(latents) hi, contiguous (B,Q,D)
__device__ __nv_bfloat16 g_latl[524288];
__device__ __nv_bfloat16 g_wqh[1048576], g_wql[1048576];   // Wq^T hi/lo [N,K]
__device__ __nv_bfloat16 g_woh[1048576], g_wol[1048576];   // Wo^T hi/lo
__device__ signed char g_wkq1[1048576], g_wkq2[1048576];   // Wk^T int8 digits [N,K]
__device__ signed char g_wvq1[1048576], g_wvq2[1048576];
__device__ float g_wks[1024], g_wvs[1024];                 // per-col weight scales
__device__ __nv_bfloat16 g_qh[524288], g_ql[524288];       // q proj hi/lo (scaled 1/8)
__device__ __nv_bfloat16 g_kh[34078720], g_kl[34078720];   // k proj hi/lo
__device__ __nv_bfloat16 g_vh[34078720], g_vl[34078720];   // v proj hi/lo
__device__ float g_opart[2097152];          // 128 bh * 4 splits * 64 * 64
__device__ float g_mpart[32768];
__device__ float g_lpart[32768];
__device__ __nv_bfloat16 g_ah[524288];
__device__ __nv_bfloat16 g_al[524288];

// ==================== helpers ==============================================
__device__ __forceinline__ uint32_t smem_u32(const void* p) {
    uint32_t a;
    asm("{ .reg .u64 t; cvta.to.shared.u64 t, %1; cvt.u32.u64 %0, t; }" : "=r"(a) : "l"(p));
    return a;
}
__device__ __forceinline__ void ldm_x4(uint32_t* r, uint32_t addr) {
    asm volatile("ldmatrix.sync.aligned.m8n8.x4.shared.b16 {%0,%1,%2,%3}, [%4];"
                 : "=r"(r[0]), "=r"(r[1]), "=r"(r[2]), "=r"(r[3]) : "r"(addr));
}
__device__ __forceinline__ void ldm_x2(uint32_t* r, uint32_t addr) {
    asm volatile("ldmatrix.sync.aligned.m8n8.x2.shared.b16 {%0,%1}, [%2];"
                 : "=r"(r[0]), "=r"(r[1]) : "r"(addr));
}
__device__ __forceinline__ void ldm_x2_t(uint32_t* r, uint32_t addr) {
    asm volatile("ldmatrix.sync.aligned.m8n8.x2.trans.shared.b16 {%0,%1}, [%2];"
                 : "=r"(r[0]), "=r"(r[1]) : "r"(addr));
}
__device__ __forceinline__ void mma_bf16(float* c, const uint32_t* a, const uint32_t* b) {
    asm volatile("mma.sync.aligned.m16n8k16.row.col.f32.bf16.bf16.f32 "
                 "{%0,%1,%2,%3}, {%4,%5,%6,%7}, {%8,%9}, {%0,%1,%2,%3};"
                 : "+f"(c[0]), "+f"(c[1]), "+f"(c[2]), "+f"(c[3])
                 : "r"(a[0]), "r"(a[1]), "r"(a[2]), "r"(a[3]), "r"(b[0]), "r"(b[1]));
}
__device__ __forceinline__ void mma_s8(int* c, const uint32_t* a, const uint32_t* b) {
    asm volatile("mma.sync.aligned.m16n8k32.row.col.s32.s8.s8.s32 "
                 "{%0,%1,%2,%3}, {%4,%5,%6,%7}, {%8,%9}, {%0,%1,%2,%3};"
                 : "+r"(c[0]), "+r"(c[1]), "+r"(c[2]), "+r"(c[3])
                 : "r"(a[0]), "r"(a[1]), "r"(a[2]), "r"(a[3]), "r"(b[0]), "r"(b[1]));
}
__device__ __forceinline__ uint32_t packbf(float lo, float hi) {
    uint32_t r;
    asm("cvt.rn.bf16x2.f32 %0, %1, %2;" : "=r"(r) : "f"(hi), "f"(lo));
    return r;
}

// ==================== LayerNorm -> int8 digits + latent bf16 pair ==========
__global__ __launch_bounds__(256) void ln_kernel(
    const float* __restrict__ feat, const float* __restrict__ lat,
    const float* __restrict__ lnm_w, const float* __restrict__ lnm_b,
    const float* __restrict__ lnl_w, const float* __restrict__ lnl_b)
{
    int r = blockIdx.x;
    int b = r / NFL, f = r - b * NFL;
    const float* src; const float* w; const float* bias;
    bool is_lat = (f >= NF);
    int ql = 0;
    if (!is_lat) { src = feat + (size_t)(b * NF + f) * ND; w = lnm_w; bias = lnm_b; }
    else { ql = f - NF; src = lat + (size_t)(b * NQ + ql) * ND; w = lnl_w; bias = lnl_b; }

    int t = threadIdx.x;
    float4 v = ((const float4*)src)[t];
    float s  = v.x + v.y + v.z + v.w;
    float ss = v.x*v.x + v.y*v.y + v.z*v.z + v.w*v.w;

    __shared__ float red[2][8];
    __shared__ float stat[2];
    __shared__ float smax[8];
    __shared__ float sAsh;
    #pragma unroll
    for (int o = 16; o > 0; o >>= 1) {
        s  += __shfl_down_sync(0xffffffffu, s,  o);
        ss += __shfl_down_sync(0xffffffffu, ss, o);
    }
    int wid = t >> 5, lid = t & 31;
    if (lid == 0) { red[0][wid] = s; red[1][wid] = ss; }
    __syncthreads();
    if (t == 0) {
        float a = 0.f, c = 0.f;
        #pragma unroll
        for (int i = 0; i < 8; i++) { a += red[0][i]; c += red[1][i]; }
        float mu  = a * (1.0f / ND);
        float var = c * (1.0f / ND) - mu * mu;
        stat[0] = mu; stat[1] = rsqrtf(var + 1e-5f);
    }
    __syncthreads();
    float mu = stat[0], inv = stat[1];
    float4 w4 = ((const float4*)w)[t];
    float4 b4 = ((const float4*)bias)[t];
    float o0 = (v.x - mu) * inv * w4.x + b4.x;
    float o1 = (v.y - mu) * inv * w4.y + b4.y;
    float o2 = (v.z - mu) * inv * w4.z + b4.z;
    float o3 = (v.w - mu) * inv * w4.w + b4.w;

    float am = fmaxf(fmaxf(fabsf(o0), fabsf(o1)), fmaxf(fabsf(o2), fabsf(o3)));
    #pragma unroll
    for (int o = 16; o > 0; o >>= 1)
        am = fmaxf(am, __shfl_down_sync(0xffffffffu, am, o));
    if (lid == 0) smax[wid] = am;
    __syncthreads();
    if (t == 0) {
        float m = 0.f;
        #pragma unroll
        for (int i = 0; i < 8; i++) m = fmaxf(m, smax[i]);
        float sA = fmaxf(m, 1e-20f) * (1.0f / 127.0f);
        sAsh = sA;
        g_xs[r] = sA;
    }
    __syncthreads();
    float sA = sAsh, isA = 1.0f / sA;

    float ov[4] = {o0, o1, o2, o3};
    signed char q1[4], q2[4];
    #pragma unroll
    for (int i = 0; i < 4; i++) {
        float a1 = rintf(ov[i] * isA);
        a1 = fminf(fmaxf(a1, -127.f), 127.f);
        float rres = ov[i] - sA * a1;
        float a2 = rintf(rres * 128.0f * isA);
        q1[i] = (signed char)(int)a1;
        q2[i] = (signed char)(int)a2;
    }
    size_t idx = (size_t)r * ND + t * 4;
    *(char4*)&g_xq1[idx] = make_char4(q1[0], q1[1], q1[2], q1[3]);
    *(char4*)&g_xq2[idx] = make_char4(q2[0], q2[1], q2[2], q2[3]);

    if (is_lat) {
        __nv_bfloat16 h0 = __float2bfloat16(o0), h1 = __float2bfloat16(o1);
        __nv_bfloat16 h2 = __float2bfloat16(o2), h3 = __float2bfloat16(o3);
        __nv_bfloat16 l0 = __float2bfloat16(o0 - __bfloat162float(h0));
        __nv_bfloat16 l1 = __float2bfloat16(o1 - __bfloat162float(h1));
        __nv_bfloat16 l2 = __float2bfloat16(o2 - __bfloat162float(h2));
        __nv_bfloat16 l3 = __float2bfloat16(o3 - __bfloat162float(h3));
        size_t li = (size_t)(b * NQ + ql) * ND + t * 4;
        *(__nv_bfloat162*)&g_lath[li]     = __nv_bfloat162{h0, h1};
        *(__nv_bfloat162*)&g_lath[li + 2] = __nv_bfloat162{h2, h3};
        *(__nv_bfloat162*)&g_latl[li]     = __nv_bfloat162{l0, l1};
        *(__nv_bfloat162*)&g_latl[li + 2] = __nv_bfloat162{l2, l3};
    }
}

// ============ bf16 weight transpose + split (Wq, Wo) =======================
__global__ __launch_bounds__(256) void wsplit_kernel(
    const float* __restrict__ W, __nv_bfloat16* __restrict__ Th,
    __nv_bfloat16* __restrict__ Tl)
{
    __shared__ float t[32][33];
    int bx = blockIdx.x * 32;
    int by = blockIdx.y * 32;
    int tx = threadIdx.x & 31, ty = threadIdx.x >> 5;
    #pragma unroll
    for (int i = 0; i < 32; i += 8)
        t[ty + i][tx] = W[(size_t)(by + ty + i) * 1024 + bx + tx];
    __syncthreads();
    #pragma unroll
    for (int i = 0; i < 32; i += 8) {
        float v = t[tx][ty + i];
        __nv_bfloat16 h = __float2bfloat16(v);
        __nv_bfloat16 l = __float2bfloat16(v - __bfloat162float(h));
        size_t o = (size_t)(bx + ty + i) * 1024 + by + tx;
        Th[o] = h; Tl[o] = l;
    }
}

// ============ per-column weight max scale (coalesced, both weights) ========
__global__ __launch_bounds__(256) void wcolmax2_kernel(
    const float* __restrict__ Wk, const float* __restrict__ Wv,
    float* __restrict__ sBk, float* __restrict__ sBv)
{
    const float* W = blockIdx.y ? Wv : Wk;
    float* sB      = blockIdx.y ? sBv : sBk;
    int n0 = blockIdx.x * 32;
    int tx = threadIdx.x & 31;           // column within group
    int ty = threadIdx.x >> 5;           // row phase 0..7
    float m = 0.f;
    for (int k = ty; k < 1024; k += 8)   // coalesced: 32 consecutive floats/warp
        m = fmaxf(m, fabsf(W[(size_t)k * 1024 + n0 + tx]));
    __shared__ float red[8][32];
    red[ty][tx] = m;
    __syncthreads();
    if (ty == 0) {
        float mm = red[0][tx];
        #pragma unroll
        for (int i = 1; i < 8; i++) mm = fmaxf(mm, red[i][tx]);
        sB[n0 + tx] = fmaxf(mm, 1e-20f) * (1.0f / 127.0f);
    }
}

// ============ int8 weight transpose + 2-digit quantize =====================
__global__ __launch_bounds__(256) void wsplit_i8_kernel(
    const float* __restrict__ W, const float* __restrict__ sB,
    signed char* __restrict__ T1, signed char* __restrict__ T2)
{
    __shared__ float t[32][33];
    int bx = blockIdx.x * 32;           // n tile
    int by = blockIdx.y * 32;           // k tile
    int tx = threadIdx.x & 31, ty = threadIdx.x >> 5;
    #pragma unroll
    for (int i = 0; i < 32; i += 8)
        t[ty + i][tx] = W[(size_t)(by + ty + i) * 1024 + bx + tx];
    __syncthreads();
    #pragma unroll
    for (int i = 0; i < 32; i += 8) {
        int n = bx + ty + i;
        float s = sB[n], is = 1.0f / s;
        float v = t[tx][ty + i];        // (k = by+tx, n)
        float a1 = rintf(v * is);
        a1 = fminf(fmaxf(a1, -127.f), 127.f);
        float rres = v - s * a1;
        float a2 = rintf(rres * 128.0f * is);
        size_t o = (size_t)n * 1024 + by + tx;
        T1[o] = (signed char)(int)a1;
        T2[o] = (signed char)(int)a2;
    }
}

// ==================== bf16 split GEMM on mma.sync (Q / O projections) ======
#define LDT 40
#define VHALVES (128 * LDT)
#define STGH (4 * VHALVES)
#define GEMM_SMEM_BYTES (2 * STGH * 2)   // 81920

__device__ __forceinline__ void cp_var(uint32_t sb, uint32_t dsth,
                                       const __nv_bfloat16* __restrict__ src,
                                       int row0, int kt, int tid)
{
    #pragma unroll
    for (int j = 0; j < 2; j++) {
        int ci = tid + j * 256;
        int row = ci >> 2, c = ci & 3;
        uint32_t so = sb + (dsth + row * LDT + c * 8) * 2;
        const __nv_bfloat16* gp = src + (size_t)(row0 + row) * 1024 + kt * 32 + c * 8;
        asm volatile("cp.async.cg.shared.global [%0], [%1], 16;" :: "r"(so), "l"(gp));
    }
}

__global__ __launch_bounds__(256)
void gemm_mma_kernel(const __nv_bfloat16* __restrict__ Ah, const __nv_bfloat16* __restrict__ Al,
                     const __nv_bfloat16* __restrict__ Bh, const __nv_bfloat16* __restrict__ Bl,
                     float* __restrict__ Cf, __nv_bfloat16* __restrict__ Ch,
                     __nv_bfloat16* __restrict__ Cl, float alpha)
{
    extern __shared__ __nv_bfloat16 smn[];
    uint32_t sb = smem_u32(smn);
    int tid = threadIdx.x;
    int lid = tid & 31;
    int wid = tid >> 5;
    int warp_m = wid >> 2;
    int warp_n = wid & 3;
    int bm = blockIdx.y * 128;
    int bn = blockIdx.x * 128;

    float acc[4][4][4];
    #pragma unroll
    for (int i = 0; i < 4; i++)
        #pragma unroll
        for (int j = 0; j < 4; j++)
            #pragma unroll
            for (int k = 0; k < 4; k++) acc[i][j][k] = 0.f;

    const int NT = 32;
    {
        uint32_t st = 0;
        cp_var(sb, st,               Ah, bm, 0, tid);
        cp_var(sb, st + VHALVES,     Al, bm, 0, tid);
        cp_var(sb, st + 2 * VHALVES, Bh, bn, 0, tid);
        cp_var(sb, st + 3 * VHALVES, Bl, bn, 0, tid);
        asm volatile("cp.async.commit_group;" ::: "memory");
    }
    int a_row = lid & 15, a_koff = (lid >> 4) * 8;
    int b_row = lid & 7,  b_koff = ((lid >> 3) & 1) * 8;

    for (int kt = 0; kt < NT; ++kt) {
        if (kt + 1 < NT) {
            uint32_t st = ((kt + 1) & 1) * STGH;
            cp_var(sb, st,               Ah, bm, kt + 1, tid);
            cp_var(sb, st + VHALVES,     Al, bm, kt + 1, tid);
            cp_var(sb, st + 2 * VHALVES, Bh, bn, kt + 1, tid);
            cp_var(sb, st + 3 * VHALVES, Bl, bn, kt + 1, tid);
            asm volatile("cp.async.commit_group;" ::: "memory");
            asm volatile("cp.async.wait_group 1;" ::: "memory");
        } else {
            asm volatile("cp.async.wait_group 0;" ::: "memory");
        }
        __syncthreads();

        uint32_t st = (kt & 1) * STGH;
        uint32_t Ah_b = sb + (st) * 2;
        uint32_t Al_b = sb + (st + VHALVES) * 2;
        uint32_t Bh_b = sb + (st + 2 * VHALVES) * 2;
        uint32_t Bl_b = sb + (st + 3 * VHALVES) * 2;

        #pragma unroll
        for (int ks = 0; ks < 2; ++ks) {
            uint32_t ah[4][4], al[4][4], bf[4][2];
            #pragma unroll
            for (int mt = 0; mt < 4; mt++) {
                uint32_t off = ((warp_m * 64 + mt * 16 + a_row) * LDT + ks * 16 + a_koff) * 2;
                ldm_x4(ah[mt], Ah_b + off);
            }
            #pragma unroll
            for (int nt = 0; nt < 4; nt++) {
                uint32_t off = ((warp_n * 32 + nt * 8 + b_row) * LDT + ks * 16 + b_koff) * 2;
                ldm_x2(bf[nt], Bh_b + off);
            }
            #pragma unroll
            for (int mt = 0; mt < 4; mt++)
                #pragma unroll
                for (int nt = 0; nt < 4; nt++) mma_bf16(acc[mt][nt], ah[mt], bf[nt]);
            #pragma unroll
            for (int mt = 0; mt < 4; mt++) {
                uint32_t off = ((warp_m * 64 + mt * 16 + a_row) * LDT + ks * 16 + a_koff) * 2;
                ldm_x4(al[mt], Al_b + off);
            }
            #pragma unroll
            for (int mt = 0; mt < 4; mt++)
                #pragma unroll
                for (int nt = 0; nt < 4; nt++) mma_bf16(acc[mt][nt], al[mt], bf[nt]);
            #pragma unroll
            for (int nt = 0; nt < 4; nt++) {
                uint32_t off = ((warp_n * 32 + nt * 8 + b_row) * LDT + ks * 16 + b_koff) * 2;
                ldm_x2(bf[nt], Bl_b + off);
            }
            #pragma unroll
            for (int mt = 0; mt < 4; mt++)
                #pragma unroll
                for (int nt = 0; nt < 4; nt++) mma_bf16(acc[mt][nt], ah[mt], bf[nt]);
        }
        __syncthreads();
    }

    int r0 = bm + warp_m * 64 + (lid >> 2);
    int c0 = bn + warp_n * 32 + (lid & 3) * 2;
    if (Cf) {
        #pragma unroll
        for (int mt = 0; mt < 4; mt++) {
            #pragma unroll
            for (int nt = 0; nt < 4; nt++) {
                float* p0 = Cf + (size_t)(r0 + mt * 16) * 1024 + c0 + nt * 8;
                float* p1 = Cf + (size_t)(r0 + mt * 16 + 8) * 1024 + c0 + nt * 8;
                *(float2*)p0 = make_float2(alpha * acc[mt][nt][0], alpha * acc[mt][nt][1]);
                *(float2*)p1 = make_float2(alpha * acc[mt][nt][2], alpha * acc[mt][nt][3]);
            }
        }
    } else {
        #pragma unroll
        for (int mt = 0; mt < 4; mt++) {
            #pragma unroll
            for (int nt = 0; nt < 4; nt++) {
                #pragma unroll
                for (int half = 0; half < 2; half++) {
                    float v0 = alpha * acc[mt][nt][half * 2];
                    float v1 = alpha * acc[mt][nt][half * 2 + 1];
                    __nv_bfloat16 h0 = __float2bfloat16(v0), h1 = __float2bfloat16(v1);
                    __nv_bfloat16 l0 = __float2bfloat16(v0 - __bfloat162float(h0));
                    __nv_bfloat16 l1 = __float2bfloat16(v1 - __bfloat162float(h1));
                    size_t o = (size_t)(r0 + mt * 16 + half * 8) * 1024 + c0 + nt * 8;
                    *(__nv_bfloat162*)&Ch[o] = __nv_bfloat162{h0, h1};
                    *(__nv_bfloat162*)&Cl[o] = __nv_bfloat162{l0, l1};
                }
            }
        }
    }
}

// ============ int8 2-digit GEMM, BK=64, K/V via blockIdx.z =================
#define QLDB 80                        // smem row stride bytes (64 data + 16 pad)
#define QTILEB (128 * QLDB)            // 10240 B per tile
#define QSTGB (4 * QTILEB)             // 40960 B per stage (A1,A2,B1,B2)
#define QSTAGES 3
#define GEMM_I8_SMEM (QSTAGES * QSTGB) // 122880

__device__ __forceinline__ void cp_stage_i8(uint32_t sb, int slot,
    const signed char* __restrict__ A1, const signed char* __restrict__ A2,
    const signed char* __restrict__ B1, const signed char* __restrict__ B2,
    int bm, int bn, int kt, int tid)
{
    uint32_t base = sb + slot * QSTGB;
    #pragma unroll
    for (int t4 = 0; t4 < 4; t4++) {
        const signed char* src = (t4 == 0) ? A1 : (t4 == 1) ? A2 : (t4 == 2) ? B1 : B2;
        int r0 = (t4 < 2) ? bm : bn;
        #pragma unroll
        for (int u = 0; u < 2; u++) {
            int idx = tid + u * 256;          // 0..511 16B chunks (128 rows x 4)
            int row = idx >> 2, c = idx & 3;
            uint32_t dst = base + t4 * QTILEB + row * QLDB + c * 16;
            const signed char* gp = src + (size_t)(r0 + row) * 1024 + kt * 64 + c * 16;
            asm volatile("cp.async.cg.shared.global [%0], [%1], 16;" :: "r"(dst), "l"(gp));
        }
    }
}

__global__ __launch_bounds__(256, 1)
void gemm_i8_kernel(const signed char* __restrict__ A1, const signed char* __restrict__ A2,
                    const float* __restrict__ sA,
                    const signed char* __restrict__ Bk1, const signed char* __restrict__ Bk2,
                    const float* __restrict__ sBk,
                    const signed char* __restrict__ Bv1, const signed char* __restrict__ Bv2,
                    const float* __restrict__ sBv,
                    __nv_bfloat16* __restrict__ Kh, __nv_bfloat16* __restrict__ Kl,
                    __nv_bfloat16* __restrict__ Vh, __nv_bfloat16* __restrict__ Vl)
{
    extern __shared__ signed char smq[];
    uint32_t sb = smem_u32(smq);
    int tid = threadIdx.x;
    int lid = tid & 31;
    int wid = tid >> 5;
    int warp_m = wid >> 2;            // 0..1 (64 rows)
    int warp_n = wid & 3;             // 0..3 (32 cols)
    int bm = blockIdx.y * 128;
    int bn = blockIdx.x * 128;
    int zv = blockIdx.z;              // 0 = K, 1 = V

    const signed char* B1 = zv ? Bv1 : Bk1;
    const signed char* B2 = zv ? Bv2 : Bk2;
    const float* sB       = zv ? sBv : sBk;
    __nv_bfloat16* Ch     = zv ? Vh : Kh;
    __nv_bfloat16* Cl     = zv ? Vl : Kl;

    int S1[4][4][4], S2[4][4][4];
    #pragma unroll
    for (int i = 0; i < 4; i++)
        #pragma unroll
        for (int j = 0; j < 4; j++)
            #pragma unroll
            for (int k = 0; k < 4; k++) { S1[i][j][k] = 0; S2[i][j][k] = 0; }

    const int NT = 16;                // 1024 / BK64
    cp_stage_i8(sb, 0, A1, A2, B1, B2, bm, bn, 0, tid);
    asm volatile("cp.async.commit_group;" ::: "memory");
    cp_stage_i8(sb, 1, A1, A2, B1, B2, bm, bn, 1, tid);
    asm volatile("cp.async.commit_group;" ::: "memory");

    int aRow  = (lid < 16) ? lid : (lid - 16);     // 0..15
    int aByte = (lid < 16) ? 0 : 16;
    int bRow  = lid & 7;
    int bByte = ((lid >> 3) & 1) * 16;

    for (int kt = 0; kt < NT; ++kt) {
        if (kt + 1 < NT) asm volatile("cp.async.wait_group 1;" ::: "memory");
        else             asm volatile("cp.async.wait_group 0;" ::: "memory");
        __syncthreads();
        if (kt + 2 < NT) {
            cp_stage_i8(sb, (kt + 2) % QSTAGES, A1, A2, B1, B2, bm, bn, kt + 2, tid);
            asm volatile("cp.async.commit_group;" ::: "memory");
        }

        uint32_t tb  = sb + (kt % QSTAGES) * QSTGB;
        uint32_t A1b = tb;
        uint32_t A2b = tb + QTILEB;
        uint32_t B1b = tb + 2 * QTILEB;
        uint32_t B2b = tb + 3 * QTILEB;

        #pragma unroll
        for (int ks = 0; ks < 2; ++ks) {          // two k32 halves of BK=64
            uint32_t a1f[4][4], a2f[4][4], b1f[4][2], b2f[4][2];
            #pragma unroll
            for (int mt = 0; mt < 4; mt++) {
                uint32_t off = (uint32_t)(warp_m * 64 + mt * 16 + aRow) * QLDB
                               + ks * 32 + aByte;
                ldm_x4(a1f[mt], A1b + off);
                ldm_x4(a2f[mt], A2b + off);
            }
            #pragma unroll
            for (int nt = 0; nt < 4; nt++) {
                uint32_t off = (uint32_t)(warp_n * 32 + nt * 8 + bRow) * QLDB
                               + ks * 32 + bByte;
                ldm_x2(b1f[nt], B1b + off);
                ldm_x2(b2f[nt], B2b + off);
            }
            #pragma unroll
            for (int mt = 0; mt < 4; mt++)
                #pragma unroll
                for (int nt = 0; nt < 4; nt++) mma_s8(S1[mt][nt], a1f[mt], b1f[nt]);
            #pragma unroll
            for (int mt = 0; mt < 4; mt++)
                #pragma unroll
                for (int nt = 0; nt < 4; nt++) mma_s8(S2[mt][nt], a1f[mt], b2f[nt]);
            #pragma unroll
            for (int mt = 0; mt < 4; mt++)
                #pragma unroll
                for (int nt = 0; nt < 4; nt++) mma_s8(S2[mt][nt], a2f[mt], b1f[nt]);
        }
        __syncthreads();
    }

    // epilogue: dequant + bf16 hi/lo
    int r0 = bm + warp_m * 64 + (lid >> 2);
    int c0 = bn + warp_n * 32 + (lid & 3) * 2;
    #pragma unroll
    for (int mt = 0; mt < 4; mt++) {
        float sa0 = sA[r0 + mt * 16];
        float sa1 = sA[r0 + mt * 16 + 8];
        #pragma unroll
        for (int nt = 0; nt < 4; nt++) {
            float sb0 = sB[c0 + nt * 8];
            float sb1 = sB[c0 + nt * 8 + 1];
            #pragma unroll
            for (int half = 0; half < 2; half++) {
                float sar = half ? sa1 : sa0;
                float v0 = sar * sb0 * ((float)S1[mt][nt][half * 2]     + (float)S2[mt][nt][half * 2]     * 0.0078125f);
                float v1 = sar * sb1 * ((float)S1[mt][nt][half * 2 + 1] + (float)S2[mt][nt][half * 2 + 1] * 0.0078125f);
                __nv_bfloat16 h0 = __float2bfloat16(v0), h1 = __float2bfloat16(v1);
                __nv_bfloat16 l0 = __float2bfloat16(v0 - __bfloat162float(h0));
                __nv_bfloat16 l1 = __float2bfloat16(v1 - __bfloat162float(h1));
                size_t o = (size_t)(r0 + mt * 16 + half * 8) * 1024 + c0 + nt * 8;
                *(__nv_bfloat162*)&Ch[o] = __nv_bfloat162{h0, h1};
                *(__nv_bfloat162*)&Cl[o] = __nv_bfloat162{l0, l1};
            }
        }
    }
}

// ==================== tensor-core flash attention, split-KV=4 ==============
#define NSPLIT 4
#define CPS 17
#define ASTR 72
#define QTILE (64 * ASTR)
#define ATTN_SMEM ((2 * QTILE + 2 * 4 * QTILE) * 2)   // 92160

__device__ __forceinline__ void stage_kv(uint32_t sb, uint32_t stbase,
    const __nv_bfloat16* kh, const __nv_bfloat16* kl,
    const __nv_bfloat16* vh, const __nv_bfloat16* vl, size_t off, int tid)
{
    const __nv_bfloat16* srcs[4] = {kh, kl, vh, vl};
    #pragma unroll
    for (int j = 0; j < 16; j++) {
        int ci = tid + j * 128;
        int tile = ci >> 9, row = (ci >> 3) & 63, c = ci & 7;
        uint32_t dst = sb + (stbase + tile * QTILE + row * ASTR) * 2 + c * 16;
        const __nv_bfloat16* src = srcs[tile] + off + (size_t)row * INNER + c * 8;
        asm volatile("cp.async.cg.shared.global [%0], [%1], 16;" :: "r"(dst), "l"(src));
    }
}

__global__ __launch_bounds__(128) void attn_kernel()
{
    extern __shared__ __nv_bfloat16 asmem[];
    uint32_t sb = smem_u32(asmem);
    const uint32_t QH = 0, QL = QTILE, ST0 = 2 * QTILE;

    int tid = threadIdx.x, lid = tid & 31, wid = tid >> 5;
    int bh = blockIdx.x, b = bh >> 4, h = bh & 15;
    int sp = blockIdx.y;
    int c0 = sp * CPS, c1 = min(65, c0 + CPS);

    const __nv_bfloat16* qhg = g_qh + (size_t)(b * NQ) * INNER + h * DHD;
    const __nv_bfloat16* qlg = g_ql + (size_t)(b * NQ) * INNER + h * DHD;
    const __nv_bfloat16* khg = g_kh + (size_t)(b * NFL) * INNER + h * DHD;
    const __nv_bfloat16* klg = g_kl + (size_t)(b * NFL) * INNER + h * DHD;
    const __nv_bfloat16* vhg = g_vh + (size_t)(b * NFL) * INNER + h * DHD;
    const __nv_bfloat16* vlg = g_vl + (size_t)(b * NFL) * INNER + h * DHD;

    #pragma unroll
    for (int j = 0; j < 8; j++) {
        int ci = tid + j * 128;
        int tile = ci >> 9, row = (ci >> 3) & 63, c = ci & 7;
        uint32_t dst = sb + ((tile ? QL : QH) + row * ASTR) * 2 + c * 16;
        const __nv_bfloat16* src = (tile ? qlg : qhg) + (size_t)row * INNER + c * 8;
        asm volatile("cp.async.cg.shared.global [%0], [%1], 16;" :: "r"(dst), "l"(src));
    }
    stage_kv(sb, ST0, khg, klg, vhg, vlg, (size_t)c0 * 64 * INNER, tid);
    asm volatile("cp.async.commit_group;" ::: "memory");

    float oc[8][4];
    #pragma unroll
    for (int i = 0; i < 8; i++)
        #pragma unroll
        for (int j = 0; j < 4; j++) oc[i][j] = 0.f;
    float m0 = -1e30f, m1 = -1e30f, l0 = 0.f, l1 = 0.f;

    uint32_t qhf[4][4], qlf[4][4];
    bool qloaded = false;

    for (int c = c0; c < c1; ++c) {
        int p = (c - c0) & 1;
        if (c + 1 < c1) {
            stage_kv(sb, ST0 + (1 - p) * 4 * QTILE, khg, klg, vhg, vlg,
                     (size_t)(c + 1) * 64 * INNER, tid);
            asm volatile("cp.async.commit_group;" ::: "memory");
            asm volatile("cp.async.wait_group 1;" ::: "memory");
        } else {
            asm volatile("cp.async.wait_group 0;" ::: "memory");
        }
        __syncthreads();

        if (!qloaded) {
            #pragma unroll
            for (int t = 0; t < 4; t++) {
                uint32_t ao = ((wid * 16 + (lid & 15)) * ASTR + t * 16 + (lid >> 4) * 8) * 2;
                ldm_x4(qhf[t], sb + QH * 2 + ao);
                ldm_x4(qlf[t], sb + QL * 2 + ao);
            }
            qloaded = true;
        }
        uint32_t stb = ST0 + p * 4 * QTILE;

        float sc[8][4];
        #pragma unroll
        for (int j = 0; j < 8; j++)
            #pragma unroll
            for (int k = 0; k < 4; k++) sc[j][k] = 0.f;
        #pragma unroll
        for (int t = 0; t < 4; t++) {
            #pragma unroll
            for (int j = 0; j < 8; j++) {
                uint32_t ko = ((8 * j + (lid & 7)) * ASTR + t * 16 + ((lid >> 3) & 1) * 8) * 2;
                uint32_t bK[2], bKl[2];
                ldm_x2(bK,  sb + stb * 2 + ko);
                ldm_x2(bKl, sb + (stb + QTILE) * 2 + ko);
                mma_bf16(sc[j], qhf[t], bK);
                mma_bf16(sc[j], qlf[t], bK);
                mma_bf16(sc[j], qhf[t], bKl);
            }
        }
        float cm0 = -1e30f, cm1 = -1e30f;
        #pragma unroll
        for (int j = 0; j < 8; j++) {
            cm0 = fmaxf(cm0, fmaxf(sc[j][0], sc[j][1]));
            cm1 = fmaxf(cm1, fmaxf(sc[j][2], sc[j][3]));
        }
        cm0 = fmaxf(cm0, __shfl_xor_sync(0xffffffffu, cm0, 1));
        cm0 = fmaxf(cm0, __shfl_xor_sync(0xffffffffu, cm0, 2));
        cm1 = fmaxf(cm1, __shfl_xor_sync(0xffffffffu, cm1, 1));
        cm1 = fmaxf(cm1, __shfl_xor_sync(0xffffffffu, cm1, 2));
        float nm0 = fmaxf(m0, cm0), nm1 = fmaxf(m1, cm1);
        float sum0 = 0.f, sum1 = 0.f;
        #pragma unroll
        for (int j = 0; j < 8; j++) {
            sc[j][0] = __expf(sc[j][0] - nm0);
            sc[j][1] = __expf(sc[j][1] - nm0);
            sc[j][2] = __expf(sc[j][2] - nm1);
            sc[j][3] = __expf(sc[j][3] - nm1);
            sum0 += sc[j][0] + sc[j][1];
            sum1 += sc[j][2] + sc[j][3];
        }
        sum0 += __shfl_xor_sync(0xffffffffu, sum0, 1);
        sum0 += __shfl_xor_sync(0xffffffffu, sum0, 2);
        sum1 += __shfl_xor_sync(0xffffffffu, sum1, 1);
        sum1 += __shfl_xor_sync(0xffffffffu, sum1, 2);
        float e0 = __expf(m0 - nm0), e1 = __expf(m1 - nm1);
        l0 = l0 * e0 + sum0; l1 = l1 * e1 + sum1;
        m0 = nm0; m1 = nm1;
        #pragma unroll
        for (int nd = 0; nd < 8; nd++) {
            oc[nd][0] *= e0; oc[nd][1] *= e0;
            oc[nd][2] *= e1; oc[nd][3] *= e1;
        }
        uint32_t vstb = stb + 2 * QTILE;
        #pragma unroll
        for (int t2 = 0; t2 < 4; t2++) {
            float ph[8], pl[8];
            #pragma unroll
            for (int u = 0; u < 2; u++) {
                #pragma unroll
                for (int k = 0; k < 4; k++) {
                    float v = sc[2 * t2 + u][k];
                    __nv_bfloat16 hb = __float2bfloat16(v);
                    float hf = __bfloat162float(hb);
                    ph[u * 4 + k] = hf;
                    pl[u * 4 + k] = v - hf;
                }
            }
            uint32_t aph[4], apl[4];
            aph[0] = packbf(ph[0], ph[1]); aph[1] = packbf(ph[2], ph[3]);
            aph[2] = packbf(ph[4], ph[5]); aph[3] = packbf(ph[6], ph[7]);
            apl[0] = packbf(pl[0], pl[1]); apl[1] = packbf(pl[2], pl[3]);
            apl[2] = packbf(pl[4], pl[5]); apl[3] = packbf(pl[6], pl[7]);
            #pragma unroll
            for (int nd = 0; nd < 8; nd++) {
                uint32_t vo = ((16 * t2 + (lid & 15)) * ASTR + nd * 8) * 2;
                uint32_t bV[2], bVl[2];
                ldm_x2_t(bV,  sb + vstb * 2 + vo);
                ldm_x2_t(bVl, sb + (vstb + QTILE) * 2 + vo);
                mma_bf16(oc[nd], aph, bV);
                mma_bf16(oc[nd], apl, bV);
                mma_bf16(oc[nd], aph, bVl);
            }
        }
        __syncthreads();
    }
    float i0 = 1.0f / l0, i1 = 1.0f / l1;
    int pidx = bh * NSPLIT + sp;
    int r0 = wid * 16 + (lid >> 2), r1 = r0 + 8;
    #pragma unroll
    for (int nd = 0; nd < 8; nd++) {
        int col = 8 * nd + (lid & 3) * 2;
        *(float2*)&g_opart[((size_t)pidx * 64 + r0) * 64 + col] =
            make_float2(oc[nd][0] * i0, oc[nd][1] * i0);
        *(float2*)&g_opart[((size_t)pidx * 64 + r1) * 64 + col] =
            make_float2(oc[nd][2] * i1, oc[nd][3] * i1);
    }
    if ((lid & 3) == 0) {
        g_mpart[pidx * 64 + r0] = m0; g_lpart[pidx * 64 + r0] = l0;
        g_mpart[pidx * 64 + r1] = m1; g_lpart[pidx * 64 + r1] = l1;
    }
}

// ---------------- merge splits -> attn out hi/lo ---------------------------
__global__ __launch_bounds__(256) void attn_merge_kernel()
{
    int bh = blockIdx.x;
    int b = bh >> 4, h = bh & 15;
    int row = threadIdx.x >> 2;
    int cg  = threadIdx.x & 3;
    float m[NSPLIT], l[NSPLIT];
    #pragma unroll
    for (int s = 0; s < NSPLIT; s++) {
        m[s] = g_mpart[(bh * NSPLIT + s) * 64 + row];
        l[s] = g_lpart[(bh * NSPLIT + s) * 64 + row];
    }
    float M = m[0];
    #pragma unroll
    for (int s = 1; s < NSPLIT; s++) M = fmaxf(M, m[s]);
    float w[NSPLIT]; float L = 0.f;
    #pragma unroll
    for (int s = 0; s < NSPLIT; s++) { w[s] = __expf(m[s] - M); L += w[s] * l[s]; }
    float inv = 1.0f / L;
    #pragma unroll
    for (int j = 0; j < 16; j++) {
        int col = cg * 16 + j;
        float acc = 0.f;
        #pragma unroll
        for (int s = 0; s < NSPLIT; s++)
            acc += g_opart[((size_t)(bh * NSPLIT + s) * 64 + row) * 64 + col] * w[s] * l[s];
        acc *= inv;
        __nv_bfloat16 hh = __float2bfloat16(acc);
        size_t oidx = (size_t)(b * NQ + row) * INNER + h * DHD + col;
        g_ah[oidx] = hh;
        g_al[oidx] = __float2bfloat16(acc - __bfloat162float(hh));
    }
}

// ==================== launcher =============================================
extern "C" void kernel_launch(void* const* d_in, const int* in_sizes, int n_in,
                              void* d_out, int out_size)
{
    const float* features = (const float*)d_in[0];
    const float* latents  = (const float*)d_in[1];
    const float* lnm_w    = (const float*)d_in[2];
    const float* lnm_b    = (const float*)d_in[3];
    const float* lnl_w    = (const float*)d_in[4];
    const float* lnl_b    = (const float*)d_in[5];
    const float* Wq       = (const float*)d_in[6];
    const float* Wk       = (const float*)d_in[7];
    const float* Wv       = (const float*)d_in[8];
    const float* Wo       = (const float*)d_in[9];
    float* out = (float*)d_out;

    __nv_bfloat16 *p_lath, *p_latl, *p_wqh, *p_wql, *p_woh, *p_wol;
    __nv_bfloat16 *p_ah, *p_al, *p_qh, *p_ql, *p_kh, *p_kl, *p_vh, *p_vl;
    signed char *p_xq1, *p_xq2, *p_wkq1, *p_wkq2, *p_wvq1, *p_wvq2;
    float *p_xs, *p_wks, *p_wvs;
    cudaGetSymbolAddress((void**)&p_lath, g_lath); cudaGetSymbolAddress((void**)&p_latl, g_latl);
    cudaGetSymbolAddress((void**)&p_wqh, g_wqh); cudaGetSymbolAddress((void**)&p_wql, g_wql);
    cudaGetSymbolAddress((void**)&p_woh, g_woh); cudaGetSymbolAddress((void**)&p_wol, g_wol);
    cudaGetSymbolAddress((void**)&p_ah, g_ah);   cudaGetSymbolAddress((void**)&p_al, g_al);
    cudaGetSymbolAddress((void**)&p_qh, g_qh);   cudaGetSymbolAddress((void**)&p_ql, g_ql);
    cudaGetSymbolAddress((void**)&p_kh, g_kh);   cudaGetSymbolAddress((void**)&p_kl, g_kl);
    cudaGetSymbolAddress((void**)&p_vh, g_vh);   cudaGetSymbolAddress((void**)&p_vl, g_vl);
    cudaGetSymbolAddress((void**)&p_xq1, g_xq1); cudaGetSymbolAddress((void**)&p_xq2, g_xq2);
    cudaGetSymbolAddress((void**)&p_wkq1, g_wkq1); cudaGetSymbolAddress((void**)&p_wkq2, g_wkq2);
    cudaGetSymbolAddress((void**)&p_wvq1, g_wvq1); cudaGetSymbolAddress((void**)&p_wvq2, g_wvq2);
    cudaGetSymbolAddress((void**)&p_xs, g_xs);
    cudaGetSymbolAddress((void**)&p_wks, g_wks); cudaGetSymbolAddress((void**)&p_wvs, g_wvs);

    cudaFuncSetAttribute(gemm_mma_kernel,
                         cudaFuncAttributeMaxDynamicSharedMemorySize, GEMM_SMEM_BYTES);
    cudaFuncSetAttribute(gemm_i8_kernel,
                         cudaFuncAttributeMaxDynamicSharedMemorySize, GEMM_I8_SMEM);
    cudaFuncSetAttribute(attn_kernel,
                         cudaFuncAttributeMaxDynamicSharedMemorySize, ATTN_SMEM);

    // 1) LayerNorm -> int8 digits (+ latent bf16 pair)
    ln_kernel<<<NB * NFL, 256>>>(features, latents, lnm_w, lnm_b, lnl_w, lnl_b);

    // 2) weight prep (coalesced colmax: one launch for Wk+Wv)
    dim3 gW(32, 32);
    wsplit_kernel<<<gW, 256>>>(Wq, p_wqh, p_wql);
    wsplit_kernel<<<gW, 256>>>(Wo, p_woh, p_wol);
    wcolmax2_kernel<<<dim3(32, 2), 256>>>(Wk, Wv, p_wks, p_wvs);
    wsplit_i8_kernel<<<gW, 256>>>(Wk, p_wks, p_wkq1, p_wkq2);
    wsplit_i8_kernel<<<gW, 256>>>(Wv, p_wvs, p_wvq1, p_wvq2);

    // 3) K + V projections: one launch, BK=64, z selects K/V
    dim3 gKV(8, MKV / 128, 2);
    gemm_i8_kernel<<<gKV, 256, GEMM_I8_SMEM>>>(p_xq1, p_xq2, p_xs,
                                               p_wkq1, p_wkq2, p_wks,
                                               p_wvq1, p_wvq2, p_wvs,
                                               p_kh, p_kl, p_vh, p_vl);

    // 4) Q projection (bf16 path, scale folded)
    dim3 gQ(8, MQ / 128);
    gemm_mma_kernel<<<gQ, 256, GEMM_SMEM_BYTES>>>(p_lath, p_latl, p_wqh, p_wql,
                                                  nullptr, p_qh, p_ql, 0.125f);

    // 5) attention split-KV=4 + merge
    dim3 gA(NB * NH, NSPLIT);
    attn_kernel<<<gA, 128, ATTN_SMEM>>>();
    attn_merge_kernel<<<NB * NH, 256>>>();

    // 6) output projection -> fp32 out
    gemm_mma_kernel<<<gQ, 256, GEMM_SMEM_BYTES>>>(p_ah, p_al, p_woh, p_wol,
                                                  out, nullptr, nullptr, 1.0f);
}